// round 1
// baseline (speedup 1.0000x reference)
#include <cuda_runtime.h>
#include <math.h>

// Problem constants
#define NN 20000
#define EE 4000
#define IND 128
#define OUTD 64
#define NH 8
#define HD 8
#define CDIM 72            // 64 weighted + 8 expn columns
#define ALPHA 0.2f

// GEMM1 tiling
#define ETILE 128
#define KC 32
#define NSPLIT 25
#define KSPLIT 800         // 25 * 800 = 20000 exactly

// ---------------- scratch (device globals; no allocation allowed) -----------
__device__ float    g_Xh[NN * OUTD];          // 5.12 MB
__device__ float    g_s[NN * NH];             // 0.64 MB
__device__ unsigned g_smax[NH];               // encoded-float max per head
__device__ float    g_Z[NN * CDIM];           // 5.76 MB
__device__ float    g_Ppart[NSPLIT * EE * CDIM]; // 28.8 MB partials
__device__ float    g_agg[EE * OUTD];         // 1.0 MB

// monotonic float<->uint encoding for atomicMax on signed floats
__device__ __forceinline__ unsigned enc_f(float f) {
    unsigned u = __float_as_uint(f);
    return (u & 0x80000000u) ? ~u : (u | 0x80000000u);
}
__device__ __forceinline__ float dec_f(unsigned u) {
    return (u & 0x80000000u) ? __uint_as_float(u ^ 0x80000000u)
                             : __uint_as_float(~u);
}

// ---------------- K0: init per-head max ------------------------------------
__global__ void k0_init() {
    int t = threadIdx.x;
    if (t < NH) g_smax[t] = 0u;   // 0 encodes the most-negative value
}

// ---------------- K1: Xh = X@W, s = leaky(Xh . a), per-head max -------------
__global__ void k1_xw(const float* __restrict__ X,
                      const float* __restrict__ W,
                      const float* __restrict__ att) {
    __shared__ float Xs[64][68];   // [k][n] transposed, padded
    __shared__ float Ws[64][64];   // [k][c]
    __shared__ float a_s[64];
    __shared__ unsigned red[NH];

    const int t = threadIdx.x;          // 256 threads
    const int nth = t & 15;
    const int ct  = t >> 4;             // 0..15
    const int n0  = blockIdx.x * 64;

    if (t < 64) {
        int h = t >> 3, d = t & 7;
        a_s[t] = att[h * 16 + d] + att[h * 16 + 8 + d];
    }
    if (t < NH) red[t] = 0u;

    float acc[4][4];
#pragma unroll
    for (int i = 0; i < 4; i++)
#pragma unroll
        for (int j = 0; j < 4; j++) acc[i][j] = 0.f;

    for (int k0 = 0; k0 < IND; k0 += 64) {
        // X tile transposed into Xs[k][n]
        for (int i = t; i < 1024; i += 256) {
            int row = i >> 4, q = i & 15;
            int n = n0 + row;
            float4 v = make_float4(0.f, 0.f, 0.f, 0.f);
            if (n < NN) v = *(const float4*)&X[(size_t)n * IND + k0 + q * 4];
            Xs[q * 4 + 0][row] = v.x;
            Xs[q * 4 + 1][row] = v.y;
            Xs[q * 4 + 2][row] = v.z;
            Xs[q * 4 + 3][row] = v.w;
        }
        // W tile direct
        for (int i = t; i < 1024; i += 256) {
            int row = i >> 4, q = i & 15;
            *(float4*)&Ws[row][q * 4] =
                *(const float4*)&W[(size_t)(k0 + row) * OUTD + q * 4];
        }
        __syncthreads();
#pragma unroll 8
        for (int k = 0; k < 64; k++) {
            float4 xv = *(const float4*)&Xs[k][nth * 4];
            float4 wv = *(const float4*)&Ws[k][ct * 4];
            float xr[4] = {xv.x, xv.y, xv.z, xv.w};
            float wr[4] = {wv.x, wv.y, wv.z, wv.w};
#pragma unroll
            for (int i = 0; i < 4; i++)
#pragma unroll
                for (int j = 0; j < 4; j++)
                    acc[i][j] = fmaf(xr[i], wr[j], acc[i][j]);
        }
        __syncthreads();
    }

    // write Xh + per-thread partial of s over this 4-col group
    float a0 = a_s[ct * 4 + 0], a1 = a_s[ct * 4 + 1];
    float a2 = a_s[ct * 4 + 2], a3 = a_s[ct * 4 + 3];
    const int lane = t & 31;
    const int h = t >> 5;               // warp id == head (ct in {2h, 2h+1})
#pragma unroll
    for (int i = 0; i < 4; i++) {
        int n = n0 + nth * 4 + i;
        if (n < NN) {
            float4 v = make_float4(acc[i][0], acc[i][1], acc[i][2], acc[i][3]);
            *(float4*)&g_Xh[(size_t)n * OUTD + ct * 4] = v;
        }
        float sp = acc[i][0] * a0 + acc[i][1] * a1 + acc[i][2] * a2 + acc[i][3] * a3;
        float other = __shfl_xor_sync(0xffffffffu, sp, 16);
        if (lane < 16) {
            float sv = sp + other;
            sv = sv > 0.f ? sv : ALPHA * sv;
            if (n < NN) {
                g_s[(size_t)n * NH + h] = sv;
                atomicMax(&red[h], enc_f(sv));
            }
        }
    }
    __syncthreads();
    if (t < NH) atomicMax(&g_smax[t], red[t]);
}

// ---------------- K2: build Z = [expn * Xh (64) | expn (8)] -----------------
__global__ void k2_z() {
    int idx = blockIdx.x * blockDim.x + threadIdx.x;
    if (idx >= NN * CDIM) return;
    int n = idx / CDIM;
    int c = idx - n * CDIM;
    int h = (c < OUTD) ? (c >> 3) : (c - OUTD);
    float mx = dec_f(g_smax[h]);
    float ex = expf(g_s[(size_t)n * NH + h] - mx);
    g_Z[idx] = (c < OUTD) ? ex * g_Xh[(size_t)n * OUTD + c] : ex;
}

// ---------------- K3: Ppart[split] = H_splitᵀ @ Z_split ---------------------
__global__ __launch_bounds__(288) void k3_gemm1(const int* __restrict__ H) {
    __shared__ float Hs[KC][ETILE];   // mask as float, [k][e]
    __shared__ float Zs[KC][CDIM];    // [k][c]

    const int t = threadIdx.x;        // 288 threads = 9 warps
    const int eth = t & 31;           // 32 edge-groups of 4
    const int ct  = t >> 5;           // warp id 0..8 -> 8 cols each
    const int e0  = blockIdx.x * ETILE;
    const int n0  = blockIdx.y * KSPLIT;

    float acc[4][8];
#pragma unroll
    for (int i = 0; i < 4; i++)
#pragma unroll
        for (int j = 0; j < 8; j++) acc[i][j] = 0.f;

    for (int kk = 0; kk < KSPLIT; kk += KC) {
        // H tile -> float mask (32 rows x 128 e)
        for (int i = t; i < KC * 32; i += 288) {
            int row = i >> 5, q = i & 31;
            int e = e0 + q * 4;
            int4 v = make_int4(0, 0, 0, 0);
            if (e < EE)
                v = *(const int4*)&H[(size_t)(n0 + kk + row) * EE + e];
            Hs[row][q * 4 + 0] = v.x > 0 ? 1.f : 0.f;
            Hs[row][q * 4 + 1] = v.y > 0 ? 1.f : 0.f;
            Hs[row][q * 4 + 2] = v.z > 0 ? 1.f : 0.f;
            Hs[row][q * 4 + 3] = v.w > 0 ? 1.f : 0.f;
        }
        // Z tile (32 x 72 = 576 float4)
        for (int i = t; i < 576; i += 288) {
            int row = i / 18, q = i - row * 18;
            *(float4*)&Zs[row][q * 4] =
                *(const float4*)&g_Z[(size_t)(n0 + kk + row) * CDIM + q * 4];
        }
        __syncthreads();
#pragma unroll 8
        for (int k = 0; k < KC; k++) {
            float4 m  = *(const float4*)&Hs[k][eth * 4];
            float4 z0 = *(const float4*)&Zs[k][ct * 8];
            float4 z1 = *(const float4*)&Zs[k][ct * 8 + 4];
            float mr[4] = {m.x, m.y, m.z, m.w};
            float zr[8] = {z0.x, z0.y, z0.z, z0.w, z1.x, z1.y, z1.z, z1.w};
#pragma unroll
            for (int i = 0; i < 4; i++)
#pragma unroll
                for (int j = 0; j < 8; j++)
                    acc[i][j] = fmaf(mr[i], zr[j], acc[i][j]);
        }
        __syncthreads();
    }
#pragma unroll
    for (int i = 0; i < 4; i++) {
        int e = e0 + eth * 4 + i;
        if (e < EE) {
            size_t base = ((size_t)blockIdx.y * EE + e) * CDIM + ct * 8;
            *(float4*)&g_Ppart[base] =
                make_float4(acc[i][0], acc[i][1], acc[i][2], acc[i][3]);
            *(float4*)&g_Ppart[base + 4] =
                make_float4(acc[i][4], acc[i][5], acc[i][6], acc[i][7]);
        }
    }
}

// ---------------- K4: reduce partials, agg = num/denom ----------------------
__global__ void k4_agg() {
    __shared__ float sm[CDIM];
    const int e = blockIdx.x;
    const int t = threadIdx.x;          // 128 threads
    if (t < CDIM) {
        float sum = 0.f;
        for (int s = 0; s < NSPLIT; s++)
            sum += g_Ppart[((size_t)s * EE + e) * CDIM + t];
        sm[t] = sum;
    }
    __syncthreads();
    if (t < OUTD) {
        int h = t >> 3;
        float d = sm[OUTD + h];
        g_agg[(size_t)e * OUTD + t] = (d > 0.f) ? sm[t] / d : 0.f;
    }
}

// ---------------- K5: out = H @ agg + bias ----------------------------------
__global__ __launch_bounds__(256) void k5_gemm2(const int* __restrict__ H,
                                                const float* __restrict__ bias,
                                                float* __restrict__ out) {
    __shared__ float Hs[32][132];   // [e_local][n_local], padded
    __shared__ float As[32][64];    // [e_local][c]

    const int t = threadIdx.x;      // 256 threads
    const int nth = t & 31;
    const int ct  = t >> 5;         // 0..7 -> 8 cols each
    const int n0  = blockIdx.x * 128;

    float acc[4][8];
#pragma unroll
    for (int i = 0; i < 4; i++)
#pragma unroll
        for (int j = 0; j < 8; j++) acc[i][j] = 0.f;

    for (int e0 = 0; e0 < EE; e0 += 32) {
        // H tile transposed (128 n x 32 e)
        for (int i = t; i < 1024; i += 256) {
            int row = i >> 3, q = i & 7;
            int n = n0 + row;
            int4 v = make_int4(0, 0, 0, 0);
            if (n < NN) v = *(const int4*)&H[(size_t)n * EE + e0 + q * 4];
            Hs[q * 4 + 0][row] = v.x > 0 ? 1.f : 0.f;
            Hs[q * 4 + 1][row] = v.y > 0 ? 1.f : 0.f;
            Hs[q * 4 + 2][row] = v.z > 0 ? 1.f : 0.f;
            Hs[q * 4 + 3][row] = v.w > 0 ? 1.f : 0.f;
        }
        // agg tile (32 x 64)
        for (int i = t; i < 512; i += 256) {
            int row = i >> 4, q = i & 15;
            *(float4*)&As[row][q * 4] =
                *(const float4*)&g_agg[(size_t)(e0 + row) * OUTD + q * 4];
        }
        __syncthreads();
#pragma unroll 8
        for (int k = 0; k < 32; k++) {
            float4 m  = *(const float4*)&Hs[k][nth * 4];
            float4 a0 = *(const float4*)&As[k][ct * 8];
            float4 a1 = *(const float4*)&As[k][ct * 8 + 4];
            float mr[4] = {m.x, m.y, m.z, m.w};
            float ar[8] = {a0.x, a0.y, a0.z, a0.w, a1.x, a1.y, a1.z, a1.w};
#pragma unroll
            for (int i = 0; i < 4; i++)
#pragma unroll
                for (int j = 0; j < 8; j++)
                    acc[i][j] = fmaf(mr[i], ar[j], acc[i][j]);
        }
        __syncthreads();
    }

    float4 b0 = *(const float4*)&bias[ct * 8];
    float4 b1 = *(const float4*)&bias[ct * 8 + 4];
#pragma unroll
    for (int i = 0; i < 4; i++) {
        int n = n0 + nth * 4 + i;
        if (n < NN) {
            size_t base = (size_t)n * OUTD + ct * 8;
            *(float4*)&out[base] = make_float4(acc[i][0] + b0.x, acc[i][1] + b0.y,
                                               acc[i][2] + b0.z, acc[i][3] + b0.w);
            *(float4*)&out[base + 4] = make_float4(acc[i][4] + b1.x, acc[i][5] + b1.y,
                                                   acc[i][6] + b1.z, acc[i][7] + b1.w);
        }
    }
}

// ---------------- launch ----------------------------------------------------
extern "C" void kernel_launch(void* const* d_in, const int* in_sizes, int n_in,
                              void* d_out, int out_size) {
    const float* X    = (const float*)d_in[0];   // [20000,128]
    const int*   H    = (const int*)  d_in[1];   // [20000,4000]
    const float* W    = (const float*)d_in[2];   // [128,64]
    const float* att  = (const float*)d_in[3];   // [1,8,16]
    const float* bias = (const float*)d_in[4];   // [64]
    float* out = (float*)d_out;

    k0_init<<<1, 32>>>();
    k1_xw<<<(NN + 63) / 64, 256>>>(X, W, att);
    k2_z<<<(NN * CDIM + 255) / 256, 256>>>();
    k3_gemm1<<<dim3((EE + ETILE - 1) / ETILE, NSPLIT), 288>>>(H);
    k4_agg<<<EE, 128>>>();
    k5_gemm2<<<(NN + 127) / 128, 256>>>(H, bias, out);
}